// round 1
// baseline (speedup 1.0000x reference)
#include <cuda_runtime.h>
#include <math.h>

// Problem constants (fixed by setup_inputs: T=512, N=16, C=768, 12 heads)
#define TCONST 512
#define LSEQ   1616         // 3*512 + 5*16
#define MLEN   1536         // 3*T
#define CDIM   768
#define NHEAD  12
#define HD     64
#define BMAX   8

// Scratch (device globals; no runtime allocation allowed)
__device__ float g_q[BMAX * NHEAD * LSEQ * HD];
__device__ float g_k[BMAX * NHEAD * LSEQ * HD];
__device__ float g_v[BMAX * NHEAD * LSEQ * HD];
__device__ float g_y[BMAX * LSEQ * CDIM];

// ---------------------------------------------------------------------------
// SGEMM: O = A[M, 768] * W[768, 768]^T + bias   (torch Linear semantics)
// 128x128 tile, BK=8, 256 threads, 8x8 micro-tile per thread.
// MODE 0: scatter to [b, h, l, d] layout. MODE 1: row-major [M, 768].
// ---------------------------------------------------------------------------
template <int MODE>
__device__ __forceinline__ void sgemm_body(
    const float* __restrict__ A, const float* __restrict__ W,
    const float* __restrict__ bias, float* __restrict__ O, int M)
{
    __shared__ float As[8][128];
    __shared__ float Bs[8][128];

    const int tid = threadIdx.x;
    const int tx  = tid & 15;
    const int ty  = tid >> 4;
    const int lr  = tid >> 1;          // 0..127
    const int lc  = (tid & 1) * 4;     // 0 or 4

    const int mBase = blockIdx.y * 128;
    const int nBase = blockIdx.x * 128;

    const int  arow = mBase + lr;
    const int  brow = nBase + lr;      // N=768, always in range
    const bool aval = (arow < M);

    const float* Ap = A + (size_t)arow * CDIM + lc;
    const float* Bp = W + (size_t)brow * CDIM + lc;

    float acc[8][8];
#pragma unroll
    for (int i = 0; i < 8; i++)
#pragma unroll
        for (int j = 0; j < 8; j++) acc[i][j] = 0.f;

    for (int k0 = 0; k0 < CDIM; k0 += 8) {
        float4 av = aval ? *(const float4*)(Ap + k0) : make_float4(0.f, 0.f, 0.f, 0.f);
        float4 bv = *(const float4*)(Bp + k0);
        As[lc + 0][lr] = av.x; As[lc + 1][lr] = av.y;
        As[lc + 2][lr] = av.z; As[lc + 3][lr] = av.w;
        Bs[lc + 0][lr] = bv.x; Bs[lc + 1][lr] = bv.y;
        Bs[lc + 2][lr] = bv.z; Bs[lc + 3][lr] = bv.w;
        __syncthreads();

#pragma unroll
        for (int kk = 0; kk < 8; kk++) {
            float4 a0 = *(const float4*)&As[kk][ty * 8];
            float4 a1 = *(const float4*)&As[kk][ty * 8 + 4];
            float4 b0 = *(const float4*)&Bs[kk][tx * 8];
            float4 b1 = *(const float4*)&Bs[kk][tx * 8 + 4];
            float ra[8] = {a0.x, a0.y, a0.z, a0.w, a1.x, a1.y, a1.z, a1.w};
            float rb[8] = {b0.x, b0.y, b0.z, b0.w, b1.x, b1.y, b1.z, b1.w};
#pragma unroll
            for (int i = 0; i < 8; i++)
#pragma unroll
                for (int j = 0; j < 8; j++)
                    acc[i][j] += ra[i] * rb[j];
        }
        __syncthreads();
    }

#pragma unroll
    for (int i = 0; i < 8; i++) {
        int m = mBase + ty * 8 + i;
        if (m >= M) continue;
        int b = m / LSEQ, l = m % LSEQ;
#pragma unroll
        for (int j = 0; j < 8; j++) {
            int n = nBase + tx * 8 + j;
            float v = acc[i][j] + bias[n];
            if (MODE == 0) {
                int h = n >> 6, d = n & 63;
                O[(((size_t)b * NHEAD + h) * LSEQ + l) * HD + d] = v;
            } else {
                O[(size_t)m * CDIM + n] = v;
            }
        }
    }
}

__global__ void __launch_bounds__(256) gemm_qkv(
    const float* __restrict__ X,
    const float* __restrict__ Wq, const float* __restrict__ Wk, const float* __restrict__ Wv,
    const float* __restrict__ bq, const float* __restrict__ bk, const float* __restrict__ bv,
    int M)
{
    int z = blockIdx.z;
    const float* W  = (z == 0) ? Wq : ((z == 1) ? Wk : Wv);
    const float* bs = (z == 0) ? bq : ((z == 1) ? bk : bv);
    float* O        = (z == 0) ? g_q : ((z == 1) ? g_k : g_v);
    sgemm_body<0>(X, W, bs, O, M);
}

__global__ void __launch_bounds__(256) gemm_proj(
    const float* __restrict__ Wp, const float* __restrict__ bp,
    float* __restrict__ out, int M)
{
    sgemm_body<1>(g_y, Wp, bp, out, M);
}

// ---------------------------------------------------------------------------
// Mask: True = blocked. Mirrors build_mask for T=512, N=16.
// ---------------------------------------------------------------------------
__device__ __forceinline__ bool blocked_qk(int q, int k)
{
    if (q >= MLEN) return k < MLEN;          // text rows: only text keys
    if (k >= MLEN) return q < TCONST;        // motion rows [T,3T) see all text
    int qb = q >> 9, kb = k >> 9;            // T = 512
    int qi = q & 511, ki = k & 511;
    if (qb == 0) return !(kb == 0 && qi >= ki);
    if (qb == 1) return (kb == 0) ? (qi < ki) : (qi <= ki);
    /* qb == 2 */ return (kb == 2) ? (qi <= ki) : (qi < ki);
}

// ---------------------------------------------------------------------------
// Flash attention (fp32): one block = 64 query rows of one (b, h).
// 256 threads as 16x16; each thread owns a 4x4 micro-tile.
// Tile-level skipping exploits the mask's block structure (T/64 = 8 tiles
// per motion block; text region starts at tile 24).
// ---------------------------------------------------------------------------
__global__ void __launch_bounds__(256) flash_attn(int B)
{
    extern __shared__ float sm[];
    float* Qst = sm;               // [64][65]  Qst[d][qr]  (transposed)
    float* Kst = Qst + 64 * 65;    // [64][65]  Kst[d][kc]  (transposed)
    float* Ps  = Kst + 64 * 65;    // [64][65]  Ps[qr][kc]
    float* Vs  = Ps  + 64 * 65;    // [64][64]  Vs[kc][d]

    const int bh = blockIdx.y;
    const int b  = bh / NHEAD, h = bh % NHEAD;
    const int qt = blockIdx.x;
    const int q0 = qt * 64;

    const size_t base = ((size_t)b * NHEAD + h) * LSEQ * HD;
    const float* Qg = g_q + base;
    const float* Kg = g_k + base;
    const float* Vg = g_v + base;

    const int tid = threadIdx.x;
    const int tx  = tid & 15;
    const int ty  = tid >> 4;
    const int lrr = tid >> 2;          // 0..63
    const int lcc = (tid & 3) * 4;     // 0,4,8,12

    // Load Q tile transposed
#pragma unroll
    for (int pass = 0; pass < 4; pass++) {
        int d0 = pass * 16 + lcc;
        int r  = q0 + lrr;
        float4 v = (r < LSEQ) ? *(const float4*)(Qg + (size_t)r * HD + d0)
                              : make_float4(0.f, 0.f, 0.f, 0.f);
        Qst[(d0 + 0) * 65 + lrr] = v.x;
        Qst[(d0 + 1) * 65 + lrr] = v.y;
        Qst[(d0 + 2) * 65 + lrr] = v.z;
        Qst[(d0 + 3) * 65 + lrr] = v.w;
    }

    float accO[4][4];
#pragma unroll
    for (int i = 0; i < 4; i++)
#pragma unroll
        for (int j = 0; j < 4; j++) accO[i][j] = 0.f;
    float mrow[4] = {-1e30f, -1e30f, -1e30f, -1e30f};
    float lrow[4] = {0.f, 0.f, 0.f, 0.f};

    const int nkt = (LSEQ + 63) >> 6;   // 26
    for (int kt = 0; kt < nkt; kt++) {
        // ---- tile-level skip (uniform across block) ----
        bool qtext = (qt >= 24), ktext = (kt >= 24);
        bool visit;
        if (qtext)       visit = ktext;
        else if (ktext)  visit = (qt >= 8);
        else             visit = ((qt & 7) >= (kt & 7)) && !((qt < 8) && (kt >= 8));
        if (!visit) continue;

        const int k0 = kt * 64;
        __syncthreads();   // previous PV reads done before overwriting tiles
#pragma unroll
        for (int pass = 0; pass < 4; pass++) {
            int d0 = pass * 16 + lcc;
            int r  = k0 + lrr;
            bool ok = (r < LSEQ);
            float4 kv = ok ? *(const float4*)(Kg + (size_t)r * HD + d0)
                           : make_float4(0.f, 0.f, 0.f, 0.f);
            Kst[(d0 + 0) * 65 + lrr] = kv.x;
            Kst[(d0 + 1) * 65 + lrr] = kv.y;
            Kst[(d0 + 2) * 65 + lrr] = kv.z;
            Kst[(d0 + 3) * 65 + lrr] = kv.w;
            float4 vv = ok ? *(const float4*)(Vg + (size_t)r * HD + d0)
                           : make_float4(0.f, 0.f, 0.f, 0.f);
            *(float4*)&Vs[lrr * 64 + d0] = vv;
        }
        __syncthreads();

        // ---- S = Q K^T (64-deep FMA loop) ----
        float s[4][4];
#pragma unroll
        for (int i = 0; i < 4; i++)
#pragma unroll
            for (int j = 0; j < 4; j++) s[i][j] = 0.f;
#pragma unroll 8
        for (int d = 0; d < HD; d++) {
            float a[4], bb[4];
#pragma unroll
            for (int i = 0; i < 4; i++) a[i]  = Qst[d * 65 + ty * 4 + i];
#pragma unroll
            for (int j = 0; j < 4; j++) bb[j] = Kst[d * 65 + tx * 4 + j];
#pragma unroll
            for (int i = 0; i < 4; i++)
#pragma unroll
                for (int j = 0; j < 4; j++)
                    s[i][j] += a[i] * bb[j];
        }

        // ---- mask + scale + row max ----
        float mx[4];
#pragma unroll
        for (int i = 0; i < 4; i++) {
            int q = q0 + ty * 4 + i;
            mx[i] = -1e30f;
#pragma unroll
            for (int j = 0; j < 4; j++) {
                int k = k0 + tx * 4 + j;
                bool blk = (q >= LSEQ) || (k >= LSEQ) || blocked_qk(q, k);
                s[i][j] = blk ? -1e30f : s[i][j] * 0.125f;   // 1/sqrt(64)
                mx[i] = fmaxf(mx[i], s[i][j]);
            }
        }
#pragma unroll
        for (int off = 8; off; off >>= 1)
#pragma unroll
            for (int i = 0; i < 4; i++)
                mx[i] = fmaxf(mx[i], __shfl_xor_sync(0xffffffffu, mx[i], off));

        float alpha[4], rsum[4];
#pragma unroll
        for (int i = 0; i < 4; i++) {
            float nm = fmaxf(mrow[i], mx[i]);
            alpha[i] = __expf(mrow[i] - nm);
            mrow[i]  = nm;
            rsum[i]  = 0.f;
        }
#pragma unroll
        for (int i = 0; i < 4; i++)
#pragma unroll
            for (int j = 0; j < 4; j++) {
                float p = (s[i][j] > -1e29f) ? __expf(s[i][j] - mrow[i]) : 0.f;
                Ps[(ty * 4 + i) * 65 + tx * 4 + j] = p;
                rsum[i] += p;
            }
#pragma unroll
        for (int off = 8; off; off >>= 1)
#pragma unroll
            for (int i = 0; i < 4; i++)
                rsum[i] += __shfl_xor_sync(0xffffffffu, rsum[i], off);
#pragma unroll
        for (int i = 0; i < 4; i++) {
            lrow[i] = lrow[i] * alpha[i] + rsum[i];
#pragma unroll
            for (int j = 0; j < 4; j++) accO[i][j] *= alpha[i];
        }
        __syncthreads();   // Ps visible to all

        // ---- O += P V ----
#pragma unroll 8
        for (int kk = 0; kk < 64; kk++) {
            float pv[4], vv[4];
#pragma unroll
            for (int i = 0; i < 4; i++) pv[i] = Ps[(ty * 4 + i) * 65 + kk];
#pragma unroll
            for (int j = 0; j < 4; j++) vv[j] = Vs[kk * 64 + tx * 4 + j];
#pragma unroll
            for (int i = 0; i < 4; i++)
#pragma unroll
                for (int j = 0; j < 4; j++)
                    accO[i][j] += pv[i] * vv[j];
        }
    }

    // ---- epilogue: y in [B, L, C] layout for the output projection ----
#pragma unroll
    for (int i = 0; i < 4; i++) {
        int q = q0 + ty * 4 + i;
        if (q >= LSEQ) continue;
        float invl = 1.f / fmaxf(lrow[i], 1e-30f);
#pragma unroll
        for (int j = 0; j < 4; j++)
            g_y[((size_t)b * LSEQ + q) * CDIM + h * HD + tx * 4 + j] = accO[i][j] * invl;
    }
}

// ---------------------------------------------------------------------------
extern "C" void kernel_launch(void* const* d_in, const int* in_sizes, int n_in,
                              void* d_out, int out_size)
{
    const float* x  = (const float*)d_in[0];
    const float* Wq = (const float*)d_in[1];
    const float* bq = (const float*)d_in[2];
    const float* Wk = (const float*)d_in[3];
    const float* bk = (const float*)d_in[4];
    const float* Wv = (const float*)d_in[5];
    const float* bv = (const float*)d_in[6];
    const float* Wp = (const float*)d_in[7];
    const float* bp = (const float*)d_in[8];
    // d_in[9] = T_motion (512), d_in[10] = N (16): fixed by setup_inputs.

    int B = in_sizes[0] / (LSEQ * CDIM);
    if (B < 1) B = 1;
    if (B > BMAX) B = BMAX;
    const int M = B * LSEQ;

    dim3 blk(256);

    // 1) fused QKV projections
    dim3 g1(CDIM / 128, (M + 127) / 128, 3);
    gemm_qkv<<<g1, blk>>>(x, Wq, Wk, Wv, bq, bk, bv, M);

    // 2) flash attention
    size_t smem = (size_t)(64 * 65 * 3 + 64 * 64) * sizeof(float);  // ~64.8 KB
    cudaFuncSetAttribute(flash_attn, cudaFuncAttributeMaxDynamicSharedMemorySize,
                         (int)smem);
    dim3 g2((LSEQ + 63) / 64, B * NHEAD);
    flash_attn<<<g2, blk, smem>>>(B);

    // 3) output projection directly into d_out
    dim3 g3(CDIM / 128, (M + 127) / 128);
    gemm_proj<<<g3, blk>>>(Wp, bp, (float*)d_out, M);
}

// round 3
// speedup vs baseline: 1.5638x; 1.5638x over previous
#include <cuda_runtime.h>
#include <cuda_bf16.h>
#include <cstdint>
#include <math.h>

// Problem constants (fixed by setup_inputs: T=512, N=16, C=768, 12 heads)
#define TCONST 512
#define LSEQ   1616         // 3*512 + 5*16
#define MLEN   1536         // 3*T
#define CDIM   768
#define NHEAD  12
#define HD     64
#define BMAX   8

// Scratch (device globals; no runtime allocation allowed)
__device__ float g_q[BMAX * NHEAD * LSEQ * HD];
__device__ float g_k[BMAX * NHEAD * LSEQ * HD];
__device__ float g_v[BMAX * NHEAD * LSEQ * HD];
__device__ float g_y[BMAX * LSEQ * CDIM];

// ---------------------------------------------------------------------------
// Helpers
// ---------------------------------------------------------------------------
__device__ __forceinline__ uint32_t smem_u32(const void* p) {
    uint32_t a;
    asm("{ .reg .u64 t; cvta.to.shared.u64 t, %1; cvt.u32.u64 %0, t; }"
        : "=r"(a) : "l"(p));
    return a;
}

// pack two fp32 -> bf16x2 hi and bf16x2 lo (residual)
__device__ __forceinline__ void split2(float x, float y, uint32_t& hi, uint32_t& lo) {
    __nv_bfloat162 h = __floats2bfloat162_rn(x, y);
    float2 hf = __bfloat1622float2(h);
    __nv_bfloat162 l = __floats2bfloat162_rn(x - hf.x, y - hf.y);
    hi = *reinterpret_cast<uint32_t*>(&h);
    lo = *reinterpret_cast<uint32_t*>(&l);
}

#define LDSM4(r, addr) asm volatile( \
    "ldmatrix.sync.aligned.m8n8.x4.shared.b16 {%0,%1,%2,%3}, [%4];" \
    : "=r"((r)[0]), "=r"((r)[1]), "=r"((r)[2]), "=r"((r)[3]) : "r"(addr))

#define MMA16816(c, a, b) asm volatile( \
    "mma.sync.aligned.m16n8k16.row.col.f32.bf16.bf16.f32 " \
    "{%0,%1,%2,%3}, {%4,%5,%6,%7}, {%8,%9}, {%0,%1,%2,%3};" \
    : "+f"((c)[0]), "+f"((c)[1]), "+f"((c)[2]), "+f"((c)[3]) \
    : "r"((a)[0]), "r"((a)[1]), "r"((a)[2]), "r"((a)[3]), "r"((b)[0]), "r"((b)[1]))

// ---------------------------------------------------------------------------
// HMMA GEMM: O = A[M,768] * W[768,768]^T + bias  (bf16 hi/lo split, 3 MMAs)
// 128x128 tile/CTA, 8 warps (2x4) each 64x32, BK=32, double-buffered SMEM.
// SMEM row stride 40 bf16 (80 B) -> conflict-free ldmatrix.
// MODE 0: scatter to [b,h,l,d]. MODE 1: row-major [M,768].
// ---------------------------------------------------------------------------
#define BK     32
#define ROWB   80                  // bytes per smem row (40 bf16)
#define TILEB  (128 * ROWB)        // 10240 B per (matrix, hi/lo) tile
#define BUFB   (4 * TILEB)         // AHI, ALO, BHI, BLO
#define GSMEM  (2 * BUFB)          // 81920 B double-buffered

template <int MODE>
__device__ __forceinline__ void hmma_gemm_body(
    const float* __restrict__ A, const float* __restrict__ W,
    const float* __restrict__ bias, float* __restrict__ O, int M)
{
    extern __shared__ char sm[];
    const uint32_t sb = smem_u32(sm);

    const int tid  = threadIdx.x;
    const int lane = tid & 31;
    const int wid  = tid >> 5;
    const int mBase = blockIdx.y * 128;
    const int nBase = blockIdx.x * 128;
    const int wm = (wid >> 2) * 64;     // warp row offset in tile
    const int wn = (wid & 3) * 32;      // warp col offset in tile

    // ldmatrix per-lane geometry
    const int a_row  = ((lane >> 3) & 1) * 8 + (lane & 7);
    const int a_koff = (lane >> 4) * 16;              // bytes
    const int b_row  = ((lane >> 4) & 1) * 8 + (lane & 7);
    const int b_koff = ((lane >> 3) & 1) * 16;        // bytes

    // staging geometry: 2 threads per row, 16 floats each
    const int  srow = tid >> 1;
    const int  scb  = (tid & 1) * 16;                 // float col base
    const bool aval = (mBase + srow) < M;
    const float* Ag = A + (size_t)(mBase + srow) * CDIM + scb;
    const float* Wg = W + (size_t)(nBase + srow) * CDIM + scb;
    const uint32_t soff = (uint32_t)srow * ROWB + (uint32_t)scb * 2;

    float acc[4][4][4];
#pragma unroll
    for (int i = 0; i < 4; i++)
#pragma unroll
        for (int j = 0; j < 4; j++)
#pragma unroll
            for (int r = 0; r < 4; r++) acc[i][j][r] = 0.f;

    float4 ra[4], rb[4];

    // ---- stage chunk 0 ----
#pragma unroll
    for (int q = 0; q < 4; q++) {
        ra[q] = aval ? *(const float4*)(Ag + q * 4) : make_float4(0.f, 0.f, 0.f, 0.f);
        rb[q] = *(const float4*)(Wg + q * 4);
    }
    // ---- store chunk 0 to buf 0 ----
    {
        char* base = sm;
#pragma unroll
        for (int q = 0; q < 4; q++) {
            uint32_t h0, l0, h1, l1;
            split2(ra[q].x, ra[q].y, h0, l0);
            split2(ra[q].z, ra[q].w, h1, l1);
            *(uint2*)(base + soff + q * 8)             = make_uint2(h0, h1);
            *(uint2*)(base + TILEB + soff + q * 8)     = make_uint2(l0, l1);
            split2(rb[q].x, rb[q].y, h0, l0);
            split2(rb[q].z, rb[q].w, h1, l1);
            *(uint2*)(base + 2 * TILEB + soff + q * 8) = make_uint2(h0, h1);
            *(uint2*)(base + 3 * TILEB + soff + q * 8) = make_uint2(l0, l1);
        }
    }
    __syncthreads();

    const int NC = CDIM / BK;   // 24
    for (int c = 0; c < NC; c++) {
        // ---- stage next chunk into registers ----
        if (c + 1 < NC) {
            const float* Ap = Ag + (c + 1) * BK;
            const float* Wp = Wg + (c + 1) * BK;
#pragma unroll
            for (int q = 0; q < 4; q++) {
                ra[q] = aval ? *(const float4*)(Ap + q * 4) : make_float4(0.f, 0.f, 0.f, 0.f);
                rb[q] = *(const float4*)(Wp + q * 4);
            }
        }

        // ---- compute from buf (c & 1) ----
        const uint32_t bufA = sb + (uint32_t)(c & 1) * BUFB;
        const uint32_t bufB = bufA + 2 * TILEB;
#pragma unroll
        for (int ks = 0; ks < 2; ks++) {
            uint32_t ah[4][4], al[4][4];
#pragma unroll
            for (int mt = 0; mt < 4; mt++) {
                uint32_t addr = bufA + (uint32_t)(wm + mt * 16 + a_row) * ROWB
                              + ks * 32 + a_koff;
                LDSM4(ah[mt], addr);
                LDSM4(al[mt], addr + TILEB);
            }
            uint32_t bh[4][2], bl[4][2];
#pragma unroll
            for (int np = 0; np < 2; np++) {
                uint32_t addr = bufB + (uint32_t)(wn + np * 16 + b_row) * ROWB
                              + ks * 32 + b_koff;
                uint32_t t[4];
                LDSM4(t, addr);
                bh[np * 2][0] = t[0]; bh[np * 2][1] = t[1];
                bh[np * 2 + 1][0] = t[2]; bh[np * 2 + 1][1] = t[3];
                LDSM4(t, addr + TILEB);
                bl[np * 2][0] = t[0]; bl[np * 2][1] = t[1];
                bl[np * 2 + 1][0] = t[2]; bl[np * 2 + 1][1] = t[3];
            }
#pragma unroll
            for (int mt = 0; mt < 4; mt++)
#pragma unroll
                for (int nt = 0; nt < 4; nt++) {
                    MMA16816(acc[mt][nt], ah[mt], bh[nt]);
                    MMA16816(acc[mt][nt], ah[mt], bl[nt]);
                    MMA16816(acc[mt][nt], al[mt], bh[nt]);
                }
        }
        __syncthreads();

        // ---- store staged chunk to the other buffer ----
        if (c + 1 < NC) {
            char* base = sm + ((c + 1) & 1) * BUFB;
#pragma unroll
            for (int q = 0; q < 4; q++) {
                uint32_t h0, l0, h1, l1;
                split2(ra[q].x, ra[q].y, h0, l0);
                split2(ra[q].z, ra[q].w, h1, l1);
                *(uint2*)(base + soff + q * 8)             = make_uint2(h0, h1);
                *(uint2*)(base + TILEB + soff + q * 8)     = make_uint2(l0, l1);
                split2(rb[q].x, rb[q].y, h0, l0);
                split2(rb[q].z, rb[q].w, h1, l1);
                *(uint2*)(base + 2 * TILEB + soff + q * 8) = make_uint2(h0, h1);
                *(uint2*)(base + 3 * TILEB + soff + q * 8) = make_uint2(l0, l1);
            }
            __syncthreads();
        }
    }

    // ---- epilogue: accumulators + bias -> global ----
#pragma unroll
    for (int mt = 0; mt < 4; mt++) {
#pragma unroll
        for (int nt = 0; nt < 4; nt++) {
            int cc = nBase + wn + nt * 8 + (lane & 3) * 2;
            float bx = bias[cc], by = bias[cc + 1];
#pragma unroll
            for (int half = 0; half < 2; half++) {
                int m = mBase + wm + mt * 16 + (lane >> 2) + half * 8;
                if (m >= M) continue;
                float2 v = make_float2(acc[mt][nt][half * 2] + bx,
                                       acc[mt][nt][half * 2 + 1] + by);
                if (MODE == 0) {
                    int b = m / LSEQ, l = m % LSEQ;
                    int h = cc >> 6, d = cc & 63;
                    *(float2*)(O + (((size_t)b * NHEAD + h) * LSEQ + l) * HD + d) = v;
                } else {
                    *(float2*)(O + (size_t)m * CDIM + cc) = v;
                }
            }
        }
    }
}

__global__ void __launch_bounds__(256) gemm_qkv(
    const float* __restrict__ X,
    const float* __restrict__ Wq, const float* __restrict__ Wk, const float* __restrict__ Wv,
    const float* __restrict__ bq, const float* __restrict__ bk, const float* __restrict__ bv,
    int M)
{
    int z = blockIdx.z;
    const float* W  = (z == 0) ? Wq : ((z == 1) ? Wk : Wv);
    const float* bs = (z == 0) ? bq : ((z == 1) ? bk : bv);
    float* O        = (z == 0) ? g_q : ((z == 1) ? g_k : g_v);
    hmma_gemm_body<0>(X, W, bs, O, M);
}

__global__ void __launch_bounds__(256) gemm_proj(
    const float* __restrict__ Wp, const float* __restrict__ bp,
    float* __restrict__ out, int M)
{
    hmma_gemm_body<1>(g_y, Wp, bp, out, M);
}

// ---------------------------------------------------------------------------
// Mask: True = blocked. Mirrors build_mask for T=512, N=16.
// ---------------------------------------------------------------------------
__device__ __forceinline__ bool blocked_qk(int q, int k)
{
    if (q >= MLEN) return k < MLEN;          // text rows: only text keys
    if (k >= MLEN) return q < TCONST;        // motion rows [T,3T) see all text
    int qb = q >> 9, kb = k >> 9;            // T = 512
    int qi = q & 511, ki = k & 511;
    if (qb == 0) return !(kb == 0 && qi >= ki);
    if (qb == 1) return (kb == 0) ? (qi < ki) : (qi <= ki);
    /* qb == 2 */ return (kb == 2) ? (qi <= ki) : (qi < ki);
}

// ---------------------------------------------------------------------------
// Flash attention (fp32): one block = 64 query rows of one (b, h).
// ---------------------------------------------------------------------------
__global__ void __launch_bounds__(256) flash_attn(int B)
{
    extern __shared__ float smf[];
    float* Qst = smf;              // [64][65]  Qst[d][qr]  (transposed)
    float* Kst = Qst + 64 * 65;    // [64][65]  Kst[d][kc]  (transposed)
    float* Ps  = Kst + 64 * 65;    // [64][65]  Ps[qr][kc]
    float* Vs  = Ps  + 64 * 65;    // [64][64]  Vs[kc][d]

    const int bh = blockIdx.y;
    const int b  = bh / NHEAD, h = bh % NHEAD;
    const int qt = blockIdx.x;
    const int q0 = qt * 64;

    const size_t base = ((size_t)b * NHEAD + h) * LSEQ * HD;
    const float* Qg = g_q + base;
    const float* Kg = g_k + base;
    const float* Vg = g_v + base;

    const int tid = threadIdx.x;
    const int tx  = tid & 15;
    const int ty  = tid >> 4;
    const int lrr = tid >> 2;          // 0..63
    const int lcc = (tid & 3) * 4;     // 0,4,8,12

#pragma unroll
    for (int pass = 0; pass < 4; pass++) {
        int d0 = pass * 16 + lcc;
        int r  = q0 + lrr;
        float4 v = (r < LSEQ) ? *(const float4*)(Qg + (size_t)r * HD + d0)
                              : make_float4(0.f, 0.f, 0.f, 0.f);
        Qst[(d0 + 0) * 65 + lrr] = v.x;
        Qst[(d0 + 1) * 65 + lrr] = v.y;
        Qst[(d0 + 2) * 65 + lrr] = v.z;
        Qst[(d0 + 3) * 65 + lrr] = v.w;
    }

    float accO[4][4];
#pragma unroll
    for (int i = 0; i < 4; i++)
#pragma unroll
        for (int j = 0; j < 4; j++) accO[i][j] = 0.f;
    float mrow[4] = {-1e30f, -1e30f, -1e30f, -1e30f};
    float lrow[4] = {0.f, 0.f, 0.f, 0.f};

    const int nkt = (LSEQ + 63) >> 6;   // 26
    for (int kt = 0; kt < nkt; kt++) {
        bool qtext = (qt >= 24), ktext = (kt >= 24);
        bool visit;
        if (qtext)       visit = ktext;
        else if (ktext)  visit = (qt >= 8);
        else             visit = ((qt & 7) >= (kt & 7)) && !((qt < 8) && (kt >= 8));
        if (!visit) continue;

        const int k0 = kt * 64;
        __syncthreads();
#pragma unroll
        for (int pass = 0; pass < 4; pass++) {
            int d0 = pass * 16 + lcc;
            int r  = k0 + lrr;
            bool ok = (r < LSEQ);
            float4 kv = ok ? *(const float4*)(Kg + (size_t)r * HD + d0)
                           : make_float4(0.f, 0.f, 0.f, 0.f);
            Kst[(d0 + 0) * 65 + lrr] = kv.x;
            Kst[(d0 + 1) * 65 + lrr] = kv.y;
            Kst[(d0 + 2) * 65 + lrr] = kv.z;
            Kst[(d0 + 3) * 65 + lrr] = kv.w;
            float4 vv = ok ? *(const float4*)(Vg + (size_t)r * HD + d0)
                           : make_float4(0.f, 0.f, 0.f, 0.f);
            *(float4*)&Vs[lrr * 64 + d0] = vv;
        }
        __syncthreads();

        float s[4][4];
#pragma unroll
        for (int i = 0; i < 4; i++)
#pragma unroll
            for (int j = 0; j < 4; j++) s[i][j] = 0.f;
#pragma unroll 8
        for (int d = 0; d < HD; d++) {
            float a[4], bb[4];
#pragma unroll
            for (int i = 0; i < 4; i++) a[i]  = Qst[d * 65 + ty * 4 + i];
#pragma unroll
            for (int j = 0; j < 4; j++) bb[j] = Kst[d * 65 + tx * 4 + j];
#pragma unroll
            for (int i = 0; i < 4; i++)
#pragma unroll
                for (int j = 0; j < 4; j++)
                    s[i][j] += a[i] * bb[j];
        }

        float mx[4];
#pragma unroll
        for (int i = 0; i < 4; i++) {
            int q = q0 + ty * 4 + i;
            mx[i] = -1e30f;
#pragma unroll
            for (int j = 0; j < 4; j++) {
                int k = k0 + tx * 4 + j;
                bool blk = (q >= LSEQ) || (k >= LSEQ) || blocked_qk(q, k);
                s[i][j] = blk ? -1e30f : s[i][j] * 0.125f;
                mx[i] = fmaxf(mx[i], s[i][j]);
            }
        }
#pragma unroll
        for (int off = 8; off; off >>= 1)
#pragma unroll
            for (int i = 0; i < 4; i++)
                mx[i] = fmaxf(mx[i], __shfl_xor_sync(0xffffffffu, mx[i], off));

        float alpha[4], rsum[4];
#pragma unroll
        for (int i = 0; i < 4; i++) {
            float nm = fmaxf(mrow[i], mx[i]);
            alpha[i] = __expf(mrow[i] - nm);
            mrow[i]  = nm;
            rsum[i]  = 0.f;
        }
#pragma unroll
        for (int i = 0; i < 4; i++)
#pragma unroll
            for (int j = 0; j < 4; j++) {
                float p = (s[i][j] > -1e29f) ? __expf(s[i][j] - mrow[i]) : 0.f;
                Ps[(ty * 4 + i) * 65 + tx * 4 + j] = p;
                rsum[i] += p;
            }
#pragma unroll
        for (int off = 8; off; off >>= 1)
#pragma unroll
            for (int i = 0; i < 4; i++)
                rsum[i] += __shfl_xor_sync(0xffffffffu, rsum[i], off);
#pragma unroll
        for (int i = 0; i < 4; i++) {
            lrow[i] = lrow[i] * alpha[i] + rsum[i];
#pragma unroll
            for (int j = 0; j < 4; j++) accO[i][j] *= alpha[i];
        }
        __syncthreads();

#pragma unroll 8
        for (int kk = 0; kk < 64; kk++) {
            float pv[4], vv[4];
#pragma unroll
            for (int i = 0; i < 4; i++) pv[i] = Ps[(ty * 4 + i) * 65 + kk];
#pragma unroll
            for (int j = 0; j < 4; j++) vv[j] = Vs[kk * 64 + tx * 4 + j];
#pragma unroll
            for (int i = 0; i < 4; i++)
#pragma unroll
                for (int j = 0; j < 4; j++)
                    accO[i][j] += pv[i] * vv[j];
        }
    }

#pragma unroll
    for (int i = 0; i < 4; i++) {
        int q = q0 + ty * 4 + i;
        if (q >= LSEQ) continue;
        float invl = 1.f / fmaxf(lrow[i], 1e-30f);
#pragma unroll
        for (int j = 0; j < 4; j++)
            g_y[((size_t)b * LSEQ + q) * CDIM + h * HD + tx * 4 + j] = accO[i][j] * invl;
    }
}

// ---------------------------------------------------------------------------
extern "C" void kernel_launch(void* const* d_in, const int* in_sizes, int n_in,
                              void* d_out, int out_size)
{
    const float* x  = (const float*)d_in[0];
    const float* Wq = (const float*)d_in[1];
    const float* bq = (const float*)d_in[2];
    const float* Wk = (const float*)d_in[3];
    const float* bk = (const float*)d_in[4];
    const float* Wv = (const float*)d_in[5];
    const float* bv = (const float*)d_in[6];
    const float* Wp = (const float*)d_in[7];
    const float* bp = (const float*)d_in[8];

    int B = in_sizes[0] / (LSEQ * CDIM);
    if (B < 1) B = 1;
    if (B > BMAX) B = BMAX;
    const int M = B * LSEQ;

    cudaFuncSetAttribute(gemm_qkv, cudaFuncAttributeMaxDynamicSharedMemorySize, GSMEM);
    cudaFuncSetAttribute(gemm_proj, cudaFuncAttributeMaxDynamicSharedMemorySize, GSMEM);
    size_t fsmem = (size_t)(64 * 65 * 3 + 64 * 64) * sizeof(float);
    cudaFuncSetAttribute(flash_attn, cudaFuncAttributeMaxDynamicSharedMemorySize, (int)fsmem);

    dim3 blk(256);

    // 1) fused QKV projections (HMMA bf16-split)
    dim3 g1(CDIM / 128, (M + 127) / 128, 3);
    gemm_qkv<<<g1, blk, GSMEM>>>(x, Wq, Wk, Wv, bq, bk, bv, M);

    // 2) flash attention (fp32)
    dim3 g2((LSEQ + 63) / 64, B * NHEAD);
    flash_attn<<<g2, blk, fsmem>>>(B);

    // 3) output projection directly into d_out
    dim3 g3(CDIM / 128, (M + 127) / 128);
    gemm_proj<<<g3, blk, GSMEM>>>(Wp, bp, (float*)d_out, M);
}

// round 5
// speedup vs baseline: 2.7037x; 1.7290x over previous
#include <cuda_runtime.h>
#include <cuda_bf16.h>
#include <cstdint>
#include <math.h>

// Problem constants (fixed by setup_inputs: T=512, N=16, C=768, 12 heads)
#define TCONST 512
#define LSEQ   1616         // 3*512 + 5*16
#define MLEN   1536         // 3*T
#define CDIM   768
#define NHEAD  12
#define HD     64
#define BMAX   8

// Scratch (device globals; no runtime allocation allowed)
__device__ float g_q[BMAX * NHEAD * LSEQ * HD];
__device__ float g_k[BMAX * NHEAD * LSEQ * HD];
__device__ float g_v[BMAX * NHEAD * LSEQ * HD];
__device__ float g_y[BMAX * LSEQ * CDIM];

// ---------------------------------------------------------------------------
// Helpers
// ---------------------------------------------------------------------------
__device__ __forceinline__ uint32_t smem_u32(const void* p) {
    uint32_t a;
    asm("{ .reg .u64 t; cvta.to.shared.u64 t, %1; cvt.u32.u64 %0, t; }"
        : "=r"(a) : "l"(p));
    return a;
}

// pack two fp32 -> bf16x2 hi and bf16x2 lo (residual)
__device__ __forceinline__ void split2(float x, float y, uint32_t& hi, uint32_t& lo) {
    __nv_bfloat162 h = __floats2bfloat162_rn(x, y);
    float2 hf = __bfloat1622float2(h);
    __nv_bfloat162 l = __floats2bfloat162_rn(x - hf.x, y - hf.y);
    hi = *reinterpret_cast<uint32_t*>(&h);
    lo = *reinterpret_cast<uint32_t*>(&l);
}

#define LDSM4(r, addr) asm volatile( \
    "ldmatrix.sync.aligned.m8n8.x4.shared.b16 {%0,%1,%2,%3}, [%4];" \
    : "=r"((r)[0]), "=r"((r)[1]), "=r"((r)[2]), "=r"((r)[3]) : "r"(addr))

#define LDSM4T(r, addr) asm volatile( \
    "ldmatrix.sync.aligned.m8n8.x4.trans.shared.b16 {%0,%1,%2,%3}, [%4];" \
    : "=r"((r)[0]), "=r"((r)[1]), "=r"((r)[2]), "=r"((r)[3]) : "r"(addr))

#define MMA16816(c, a, b) asm volatile( \
    "mma.sync.aligned.m16n8k16.row.col.f32.bf16.bf16.f32 " \
    "{%0,%1,%2,%3}, {%4,%5,%6,%7}, {%8,%9}, {%0,%1,%2,%3};" \
    : "+f"((c)[0]), "+f"((c)[1]), "+f"((c)[2]), "+f"((c)[3]) \
    : "r"((a)[0]), "r"((a)[1]), "r"((a)[2]), "r"((a)[3]), "r"((b)[0]), "r"((b)[1]))

// ---------------------------------------------------------------------------
// HMMA GEMM: O = A[M,768] * W[768,768]^T + bias  (bf16 hi/lo split, 3 MMAs)
// 128x128 tile/CTA, 8 warps (2x4) each 64x32, BK=32, double-buffered SMEM.
// ---------------------------------------------------------------------------
#define BK     32
#define ROWB   80                  // bytes per smem row (40 bf16)
#define TILEB  (128 * ROWB)        // 10240 B per (matrix, hi/lo) tile
#define BUFB   (4 * TILEB)         // AHI, ALO, BHI, BLO
#define GSMEM  (2 * BUFB)          // 81920 B double-buffered

template <int MODE>
__device__ __forceinline__ void hmma_gemm_body(
    const float* __restrict__ A, const float* __restrict__ W,
    const float* __restrict__ bias, float* __restrict__ O, int M)
{
    extern __shared__ char sm[];
    const uint32_t sb = smem_u32(sm);

    const int tid  = threadIdx.x;
    const int lane = tid & 31;
    const int wid  = tid >> 5;
    const int mBase = blockIdx.y * 128;
    const int nBase = blockIdx.x * 128;
    const int wm = (wid >> 2) * 64;
    const int wn = (wid & 3) * 32;

    const int a_row  = ((lane >> 3) & 1) * 8 + (lane & 7);
    const int a_koff = (lane >> 4) * 16;
    const int b_row  = ((lane >> 4) & 1) * 8 + (lane & 7);
    const int b_koff = ((lane >> 3) & 1) * 16;

    const int  srow = tid >> 1;
    const int  scb  = (tid & 1) * 16;
    const bool aval = (mBase + srow) < M;
    const float* Ag = A + (size_t)(mBase + srow) * CDIM + scb;
    const float* Wg = W + (size_t)(nBase + srow) * CDIM + scb;
    const uint32_t soff = (uint32_t)srow * ROWB + (uint32_t)scb * 2;

    float acc[4][4][4];
#pragma unroll
    for (int i = 0; i < 4; i++)
#pragma unroll
        for (int j = 0; j < 4; j++)
#pragma unroll
            for (int r = 0; r < 4; r++) acc[i][j][r] = 0.f;

    float4 ra[4], rb[4];
#pragma unroll
    for (int q = 0; q < 4; q++) {
        ra[q] = aval ? *(const float4*)(Ag + q * 4) : make_float4(0.f, 0.f, 0.f, 0.f);
        rb[q] = *(const float4*)(Wg + q * 4);
    }
    {
        char* base = sm;
#pragma unroll
        for (int q = 0; q < 4; q++) {
            uint32_t h0, l0, h1, l1;
            split2(ra[q].x, ra[q].y, h0, l0);
            split2(ra[q].z, ra[q].w, h1, l1);
            *(uint2*)(base + soff + q * 8)             = make_uint2(h0, h1);
            *(uint2*)(base + TILEB + soff + q * 8)     = make_uint2(l0, l1);
            split2(rb[q].x, rb[q].y, h0, l0);
            split2(rb[q].z, rb[q].w, h1, l1);
            *(uint2*)(base + 2 * TILEB + soff + q * 8) = make_uint2(h0, h1);
            *(uint2*)(base + 3 * TILEB + soff + q * 8) = make_uint2(l0, l1);
        }
    }
    __syncthreads();

    const int NC = CDIM / BK;   // 24
    for (int c = 0; c < NC; c++) {
        if (c + 1 < NC) {
            const float* Ap = Ag + (c + 1) * BK;
            const float* Wp = Wg + (c + 1) * BK;
#pragma unroll
            for (int q = 0; q < 4; q++) {
                ra[q] = aval ? *(const float4*)(Ap + q * 4) : make_float4(0.f, 0.f, 0.f, 0.f);
                rb[q] = *(const float4*)(Wp + q * 4);
            }
        }

        const uint32_t bufA = sb + (uint32_t)(c & 1) * BUFB;
        const uint32_t bufB = bufA + 2 * TILEB;
#pragma unroll
        for (int ks = 0; ks < 2; ks++) {
            uint32_t ah[4][4], al[4][4];
#pragma unroll
            for (int mt = 0; mt < 4; mt++) {
                uint32_t addr = bufA + (uint32_t)(wm + mt * 16 + a_row) * ROWB
                              + ks * 32 + a_koff;
                LDSM4(ah[mt], addr);
                LDSM4(al[mt], addr + TILEB);
            }
            uint32_t bh[4][2], bl[4][2];
#pragma unroll
            for (int np = 0; np < 2; np++) {
                uint32_t addr = bufB + (uint32_t)(wn + np * 16 + b_row) * ROWB
                              + ks * 32 + b_koff;
                uint32_t t[4];
                LDSM4(t, addr);
                bh[np * 2][0] = t[0]; bh[np * 2][1] = t[1];
                bh[np * 2 + 1][0] = t[2]; bh[np * 2 + 1][1] = t[3];
                LDSM4(t, addr + TILEB);
                bl[np * 2][0] = t[0]; bl[np * 2][1] = t[1];
                bl[np * 2 + 1][0] = t[2]; bl[np * 2 + 1][1] = t[3];
            }
#pragma unroll
            for (int mt = 0; mt < 4; mt++)
#pragma unroll
                for (int nt = 0; nt < 4; nt++) {
                    MMA16816(acc[mt][nt], ah[mt], bh[nt]);
                    MMA16816(acc[mt][nt], ah[mt], bl[nt]);
                    MMA16816(acc[mt][nt], al[mt], bh[nt]);
                }
        }
        __syncthreads();

        if (c + 1 < NC) {
            char* base = sm + ((c + 1) & 1) * BUFB;
#pragma unroll
            for (int q = 0; q < 4; q++) {
                uint32_t h0, l0, h1, l1;
                split2(ra[q].x, ra[q].y, h0, l0);
                split2(ra[q].z, ra[q].w, h1, l1);
                *(uint2*)(base + soff + q * 8)             = make_uint2(h0, h1);
                *(uint2*)(base + TILEB + soff + q * 8)     = make_uint2(l0, l1);
                split2(rb[q].x, rb[q].y, h0, l0);
                split2(rb[q].z, rb[q].w, h1, l1);
                *(uint2*)(base + 2 * TILEB + soff + q * 8) = make_uint2(h0, h1);
                *(uint2*)(base + 3 * TILEB + soff + q * 8) = make_uint2(l0, l1);
            }
            __syncthreads();
        }
    }

#pragma unroll
    for (int mt = 0; mt < 4; mt++) {
#pragma unroll
        for (int nt = 0; nt < 4; nt++) {
            int cc = nBase + wn + nt * 8 + (lane & 3) * 2;
            float bx = bias[cc], by = bias[cc + 1];
#pragma unroll
            for (int half = 0; half < 2; half++) {
                int m = mBase + wm + mt * 16 + (lane >> 2) + half * 8;
                if (m >= M) continue;
                float2 v = make_float2(acc[mt][nt][half * 2] + bx,
                                       acc[mt][nt][half * 2 + 1] + by);
                if (MODE == 0) {
                    int b = m / LSEQ, l = m % LSEQ;
                    int h = cc >> 6, d = cc & 63;
                    *(float2*)(O + (((size_t)b * NHEAD + h) * LSEQ + l) * HD + d) = v;
                } else {
                    *(float2*)(O + (size_t)m * CDIM + cc) = v;
                }
            }
        }
    }
}

__global__ void __launch_bounds__(256) gemm_qkv(
    const float* __restrict__ X,
    const float* __restrict__ Wq, const float* __restrict__ Wk, const float* __restrict__ Wv,
    const float* __restrict__ bq, const float* __restrict__ bk, const float* __restrict__ bv,
    int M)
{
    int z = blockIdx.z;
    const float* W  = (z == 0) ? Wq : ((z == 1) ? Wk : Wv);
    const float* bs = (z == 0) ? bq : ((z == 1) ? bk : bv);
    float* O        = (z == 0) ? g_q : ((z == 1) ? g_k : g_v);
    hmma_gemm_body<0>(X, W, bs, O, M);
}

__global__ void __launch_bounds__(256) gemm_proj(
    const float* __restrict__ Wp, const float* __restrict__ bp,
    float* __restrict__ out, int M)
{
    hmma_gemm_body<1>(g_y, Wp, bp, out, M);
}

// ---------------------------------------------------------------------------
// Mask: True = blocked. Mirrors build_mask for T=512, N=16.
// ---------------------------------------------------------------------------
__device__ __forceinline__ bool blocked_qk(int q, int k)
{
    if (q >= MLEN) return k < MLEN;
    if (k >= MLEN) return q < TCONST;
    int qb = q >> 9, kb = k >> 9;
    int qi = q & 511, ki = k & 511;
    if (qb == 0) return !(kb == 0 && qi >= ki);
    if (qb == 1) return (kb == 0) ? (qi < ki) : (qi <= ki);
    return (kb == 2) ? (qi <= ki) : (qi < ki);
}

// ---------------------------------------------------------------------------
// HMMA flash attention: CTA = 64 q-rows of one (b,h), 4 warps x 16 rows.
// bf16 hi/lo split for Q*K^T and P*V (3 MMAs each). P stays in registers.
// ---------------------------------------------------------------------------
#define FROWB 144                        // 64 dims bf16 (128B) + 16B pad
#define FTILE (64 * FROWB)               // 9216 B
#define FSMEM (4 * FTILE)                // khi, klo, vhi, vlo = 36864 B

__global__ void __launch_bounds__(128) flash_attn_mma(int B)
{
    extern __shared__ char smx[];
    const uint32_t sb  = smem_u32(smx);
    const uint32_t khi = sb;
    const uint32_t vhi = sb + 2 * FTILE;

    const int bh = blockIdx.y;
    const int b  = bh / NHEAD, h = bh % NHEAD;
    const int qt = blockIdx.x;
    const int q0 = qt * 64;

    const size_t base = ((size_t)b * NHEAD + h) * LSEQ * HD;
    const float* Qg = g_q + base;
    const float* Kg = g_k + base;
    const float* Vg = g_v + base;

    const int tid  = threadIdx.x;
    const int lane = tid & 31;
    const int g    = lane >> 2;
    const int qr   = (lane & 3) * 2;

    const int b_row  = ((lane >> 4) & 1) * 8 + (lane & 7);
    const int b_koff = ((lane >> 3) & 1) * 16;

    const int qrow0 = q0 + (tid >> 5) * 16 + g;
    const int qrow1 = qrow0 + 8;

    // ---- Q fragments (pre-scaled by 1/8, split), kept in registers ----
    uint32_t qh[4][4], ql[4][4];
#pragma unroll
    for (int ks = 0; ks < 4; ks++) {
#pragma unroll
        for (int part = 0; part < 4; part++) {
            int row = (part & 1) ? qrow1 : qrow0;
            int col = ks * 16 + qr + (part >> 1) * 8;
            float2 v = make_float2(0.f, 0.f);
            if (row < LSEQ) v = *(const float2*)(Qg + (size_t)row * HD + col);
            split2(v.x * 0.125f, v.y * 0.125f, qh[ks][part], ql[ks][part]);
        }
    }

    float oacc[8][4];
#pragma unroll
    for (int i = 0; i < 8; i++)
#pragma unroll
        for (int r = 0; r < 4; r++) oacc[i][r] = 0.f;
    float m0 = -1e30f, m1 = -1e30f, l0 = 0.f, l1 = 0.f;

    const int nkt = 26;
    for (int kt = 0; kt < nkt; kt++) {
        bool qtext = (qt >= 24), ktext = (kt >= 24);
        bool visit;
        if (qtext)       visit = ktext;
        else if (ktext)  visit = (qt >= 8);
        else             visit = ((qt & 7) >= (kt & 7)) && !((qt < 8) && (kt >= 8));
        if (!visit) continue;

        const bool partial = (kt == 25) || (!ktext && !qtext && ((qt & 7) == (kt & 7)));
        const int k0 = kt * 64;

        // ---- load K/V tile (bf16 split) ----
        __syncthreads();
#pragma unroll
        for (int i = 0; i < 8; i++) {
            int idx = tid + i * 128;         // 0..1023
            int r   = idx >> 4;
            int c4  = (idx & 15) << 2;       // dim base (float4)
            uint32_t off = (uint32_t)r * FROWB + (uint32_t)c4 * 2;
            bool ok = (k0 + r) < LSEQ;
            float4 kv = ok ? *(const float4*)(Kg + (size_t)(k0 + r) * HD + c4)
                           : make_float4(0.f, 0.f, 0.f, 0.f);
            uint32_t h0, lo0, h1, lo1;
            split2(kv.x, kv.y, h0, lo0);
            split2(kv.z, kv.w, h1, lo1);
            *(uint2*)(smx + off)             = make_uint2(h0, h1);
            *(uint2*)(smx + FTILE + off)     = make_uint2(lo0, lo1);
            float4 vv = ok ? *(const float4*)(Vg + (size_t)(k0 + r) * HD + c4)
                           : make_float4(0.f, 0.f, 0.f, 0.f);
            split2(vv.x, vv.y, h0, lo0);
            split2(vv.z, vv.w, h1, lo1);
            *(uint2*)(smx + 2 * FTILE + off) = make_uint2(h0, h1);
            *(uint2*)(smx + 3 * FTILE + off) = make_uint2(lo0, lo1);
        }
        __syncthreads();

        // ---- S = Q K^T ----
        float sacc[8][4];
#pragma unroll
        for (int i = 0; i < 8; i++)
#pragma unroll
            for (int r = 0; r < 4; r++) sacc[i][r] = 0.f;
#pragma unroll
        for (int ks = 0; ks < 4; ks++) {
#pragma unroll
            for (int kg = 0; kg < 4; kg++) {
                uint32_t addr = khi + (uint32_t)(kg * 16 + b_row) * FROWB
                              + ks * 32 + b_koff;
                uint32_t th[4], tl[4];
                LDSM4(th, addr);
                LDSM4(tl, addr + FTILE);
                uint32_t bh0[2] = {th[0], th[1]}, bh1[2] = {th[2], th[3]};
                uint32_t bl0[2] = {tl[0], tl[1]}, bl1[2] = {tl[2], tl[3]};
                MMA16816(sacc[kg * 2],     qh[ks], bh0);
                MMA16816(sacc[kg * 2],     qh[ks], bl0);
                MMA16816(sacc[kg * 2],     ql[ks], bh0);
                MMA16816(sacc[kg * 2 + 1], qh[ks], bh1);
                MMA16816(sacc[kg * 2 + 1], qh[ks], bl1);
                MMA16816(sacc[kg * 2 + 1], ql[ks], bh1);
            }
        }

        // ---- mask (partial tiles only) ----
        if (partial) {
#pragma unroll
            for (int nt = 0; nt < 8; nt++) {
                int kc = k0 + nt * 8 + qr;
#pragma unroll
                for (int e = 0; e < 2; e++) {
                    int kk = kc + e;
                    bool kb = (kk >= LSEQ);
                    if (kb || qrow0 >= LSEQ || blocked_qk(qrow0, kk))
                        sacc[nt][e] = -1e30f;
                    if (kb || qrow1 >= LSEQ || blocked_qk(qrow1, kk))
                        sacc[nt][2 + e] = -1e30f;
                }
            }
        }

        // ---- online softmax ----
        float mx0 = -1e30f, mx1 = -1e30f;
#pragma unroll
        for (int nt = 0; nt < 8; nt++) {
            mx0 = fmaxf(mx0, fmaxf(sacc[nt][0], sacc[nt][1]));
            mx1 = fmaxf(mx1, fmaxf(sacc[nt][2], sacc[nt][3]));
        }
        mx0 = fmaxf(mx0, __shfl_xor_sync(0xffffffffu, mx0, 1));
        mx0 = fmaxf(mx0, __shfl_xor_sync(0xffffffffu, mx0, 2));
        mx1 = fmaxf(mx1, __shfl_xor_sync(0xffffffffu, mx1, 1));
        mx1 = fmaxf(mx1, __shfl_xor_sync(0xffffffffu, mx1, 2));

        float nm0 = fmaxf(m0, mx0), nm1 = fmaxf(m1, mx1);
        float al0 = __expf(m0 - nm0), al1 = __expf(m1 - nm1);
        m0 = nm0; m1 = nm1;

        float rs0 = 0.f, rs1 = 0.f;
        uint32_t ph[4][4], pl[4][4];
#pragma unroll
        for (int nt = 0; nt < 8; nt++) {
            float p0 = __expf(sacc[nt][0] - nm0);
            float p1 = __expf(sacc[nt][1] - nm0);
            float p2 = __expf(sacc[nt][2] - nm1);
            float p3 = __expf(sacc[nt][3] - nm1);
            rs0 += p0 + p1; rs1 += p2 + p3;
            int j = nt >> 1, half = nt & 1;     // kstep j, a-reg pair
            split2(p0, p1, ph[j][half * 2],     pl[j][half * 2]);
            split2(p2, p3, ph[j][half * 2 + 1], pl[j][half * 2 + 1]);
        }
        rs0 += __shfl_xor_sync(0xffffffffu, rs0, 1);
        rs0 += __shfl_xor_sync(0xffffffffu, rs0, 2);
        rs1 += __shfl_xor_sync(0xffffffffu, rs1, 1);
        rs1 += __shfl_xor_sync(0xffffffffu, rs1, 2);
        l0 = l0 * al0 + rs0;
        l1 = l1 * al1 + rs1;

#pragma unroll
        for (int nt = 0; nt < 8; nt++) {
            oacc[nt][0] *= al0; oacc[nt][1] *= al0;
            oacc[nt][2] *= al1; oacc[nt][3] *= al1;
        }

        // ---- O += P V ----
#pragma unroll
        for (int j = 0; j < 4; j++) {          // key ksteps
#pragma unroll
            for (int dg = 0; dg < 4; dg++) {   // 16-dim groups
                uint32_t addr = vhi + (uint32_t)(j * 16 + b_row) * FROWB
                              + dg * 32 + b_koff;
                uint32_t th[4], tl[4];
                LDSM4T(th, addr);
                LDSM4T(tl, addr + FTILE);
                uint32_t bh0[2] = {th[0], th[2]}, bh1[2] = {th[1], th[3]};
                uint32_t bl0[2] = {tl[0], tl[2]}, bl1[2] = {tl[1], tl[3]};
                MMA16816(oacc[dg * 2],     ph[j], bh0);
                MMA16816(oacc[dg * 2],     ph[j], bl0);
                MMA16816(oacc[dg * 2],     pl[j], bh0);
                MMA16816(oacc[dg * 2 + 1], ph[j], bh1);
                MMA16816(oacc[dg * 2 + 1], ph[j], bl1);
                MMA16816(oacc[dg * 2 + 1], pl[j], bh1);
            }
        }
    }

    // ---- epilogue ----
    float inv0 = 1.f / fmaxf(l0, 1e-30f);
    float inv1 = 1.f / fmaxf(l1, 1e-30f);
#pragma unroll
    for (int nt = 0; nt < 8; nt++) {
        int d = nt * 8 + qr;
        if (qrow0 < LSEQ)
            *(float2*)(g_y + ((size_t)b * LSEQ + qrow0) * CDIM + h * HD + d)
                = make_float2(oacc[nt][0] * inv0, oacc[nt][1] * inv0);
        if (qrow1 < LSEQ)
            *(float2*)(g_y + ((size_t)b * LSEQ + qrow1) * CDIM + h * HD + d)
                = make_float2(oacc[nt][2] * inv1, oacc[nt][3] * inv1);
    }
}

// ---------------------------------------------------------------------------
extern "C" void kernel_launch(void* const* d_in, const int* in_sizes, int n_in,
                              void* d_out, int out_size)
{
    const float* x  = (const float*)d_in[0];
    const float* Wq = (const float*)d_in[1];
    const float* bq = (const float*)d_in[2];
    const float* Wk = (const float*)d_in[3];
    const float* bk = (const float*)d_in[4];
    const float* Wv = (const float*)d_in[5];
    const float* bv = (const float*)d_in[6];
    const float* Wp = (const float*)d_in[7];
    const float* bp = (const float*)d_in[8];

    int B = in_sizes[0] / (LSEQ * CDIM);
    if (B < 1) B = 1;
    if (B > BMAX) B = BMAX;
    const int M = B * LSEQ;

    cudaFuncSetAttribute(gemm_qkv, cudaFuncAttributeMaxDynamicSharedMemorySize, GSMEM);
    cudaFuncSetAttribute(gemm_proj, cudaFuncAttributeMaxDynamicSharedMemorySize, GSMEM);
    cudaFuncSetAttribute(flash_attn_mma, cudaFuncAttributeMaxDynamicSharedMemorySize, FSMEM);

    // 1) fused QKV projections (HMMA bf16-split)
    dim3 g1(CDIM / 128, (M + 127) / 128, 3);
    gemm_qkv<<<g1, dim3(256), GSMEM>>>(x, Wq, Wk, Wv, bq, bk, bv, M);

    // 2) flash attention (HMMA bf16-split)
    dim3 g2(26, B * NHEAD);
    flash_attn_mma<<<g2, dim3(128), FSMEM>>>(B);

    // 3) output projection directly into d_out
    dim3 g3(CDIM / 128, (M + 127) / 128);
    gemm_proj<<<g3, dim3(256), GSMEM>>>(Wp, bp, (float*)d_out, M);
}

// round 6
// speedup vs baseline: 3.0529x; 1.1292x over previous
#include <cuda_runtime.h>
#include <cuda_bf16.h>
#include <cstdint>
#include <math.h>

// Problem constants (fixed by setup_inputs: T=512, N=16, C=768, 12 heads)
#define TCONST 512
#define LSEQ   1616         // 3*512 + 5*16
#define MLEN   1536         // 3*T
#define CDIM   768
#define NHEAD  12
#define HD     64
#define BMAX   8

// Scratch (device globals; no runtime allocation allowed)
__device__ __nv_bfloat16 g_xh[BMAX * LSEQ * CDIM];
__device__ __nv_bfloat16 g_xl[BMAX * LSEQ * CDIM];
__device__ __nv_bfloat16 g_wh[4 * CDIM * CDIM];
__device__ __nv_bfloat16 g_wl[4 * CDIM * CDIM];
__device__ __nv_bfloat16 g_qh[BMAX * NHEAD * LSEQ * HD];
__device__ __nv_bfloat16 g_ql[BMAX * NHEAD * LSEQ * HD];
__device__ __nv_bfloat16 g_kh[BMAX * NHEAD * LSEQ * HD];
__device__ __nv_bfloat16 g_kl[BMAX * NHEAD * LSEQ * HD];
__device__ __nv_bfloat16 g_vh[BMAX * NHEAD * LSEQ * HD];
__device__ __nv_bfloat16 g_vl[BMAX * NHEAD * LSEQ * HD];
__device__ __nv_bfloat16 g_yh[BMAX * LSEQ * CDIM];
__device__ __nv_bfloat16 g_yl[BMAX * LSEQ * CDIM];

// ---------------------------------------------------------------------------
// Helpers
// ---------------------------------------------------------------------------
__device__ __forceinline__ uint32_t smem_u32(const void* p) {
    uint32_t a;
    asm("{ .reg .u64 t; cvta.to.shared.u64 t, %1; cvt.u32.u64 %0, t; }"
        : "=r"(a) : "l"(p));
    return a;
}

__device__ __forceinline__ void split2(float x, float y, uint32_t& hi, uint32_t& lo) {
    __nv_bfloat162 h = __floats2bfloat162_rn(x, y);
    float2 hf = __bfloat1622float2(h);
    __nv_bfloat162 l = __floats2bfloat162_rn(x - hf.x, y - hf.y);
    hi = *reinterpret_cast<uint32_t*>(&h);
    lo = *reinterpret_cast<uint32_t*>(&l);
}

#define LDSM4(r, addr) asm volatile( \
    "ldmatrix.sync.aligned.m8n8.x4.shared.b16 {%0,%1,%2,%3}, [%4];" \
    : "=r"((r)[0]), "=r"((r)[1]), "=r"((r)[2]), "=r"((r)[3]) : "r"(addr))

#define LDSM4T(r, addr) asm volatile( \
    "ldmatrix.sync.aligned.m8n8.x4.trans.shared.b16 {%0,%1,%2,%3}, [%4];" \
    : "=r"((r)[0]), "=r"((r)[1]), "=r"((r)[2]), "=r"((r)[3]) : "r"(addr))

#define MMA16816(c, a, b) asm volatile( \
    "mma.sync.aligned.m16n8k16.row.col.f32.bf16.bf16.f32 " \
    "{%0,%1,%2,%3}, {%4,%5,%6,%7}, {%8,%9}, {%0,%1,%2,%3};" \
    : "+f"((c)[0]), "+f"((c)[1]), "+f"((c)[2]), "+f"((c)[3]) \
    : "r"((a)[0]), "r"((a)[1]), "r"((a)[2]), "r"((a)[3]), "r"((b)[0]), "r"((b)[1]))

#define CPA16(dst, src, sz) asm volatile( \
    "cp.async.ca.shared.global [%0], [%1], 16, %2;" \
    :: "r"(dst), "l"(src), "r"(sz) : "memory")
#define CPA_COMMIT() asm volatile("cp.async.commit_group;" ::: "memory")
#define CPA_WAIT(n)  asm volatile("cp.async.wait_group %0;" :: "n"(n) : "memory")

// ---------------------------------------------------------------------------
// Pre-split kernels: fp32 -> bf16 hi/lo
// ---------------------------------------------------------------------------
__global__ void __launch_bounds__(256) split_x(const float* __restrict__ s, int n)
{
    int i = (blockIdx.x * 256 + threadIdx.x) * 4;
    if (i >= n) return;
    float4 v = *(const float4*)(s + i);
    uint32_t h0, l0, h1, l1;
    split2(v.x, v.y, h0, l0);
    split2(v.z, v.w, h1, l1);
    *(uint2*)(g_xh + i) = make_uint2(h0, h1);
    *(uint2*)(g_xl + i) = make_uint2(l0, l1);
}

__global__ void __launch_bounds__(256) split_w(
    const float* __restrict__ wq, const float* __restrict__ wk,
    const float* __restrict__ wv, const float* __restrict__ wp)
{
    int z = blockIdx.z;
    const float* s = (z == 0) ? wq : (z == 1) ? wk : (z == 2) ? wv : wp;
    int i = (blockIdx.x * 256 + threadIdx.x) * 4;
    float4 v = *(const float4*)(s + i);
    uint32_t h0, l0, h1, l1;
    split2(v.x, v.y, h0, l0);
    split2(v.z, v.w, h1, l1);
    size_t o = (size_t)z * CDIM * CDIM + i;
    *(uint2*)(g_wh + o) = make_uint2(h0, h1);
    *(uint2*)(g_wl + o) = make_uint2(l0, l1);
}

// ---------------------------------------------------------------------------
// HMMA GEMM on pre-split bf16: O = A * W^T + bias   (3 MMAs hi/lo)
// 128x128 tile/CTA, 8 warps (2x4) each 64x32, BK=32, cp.async double buffer.
// MODE 0: epilogue splits result and scatters bf16 hi/lo to [b,h,l,d].
// MODE 1: epilogue writes fp32 row-major [M,768].
// ---------------------------------------------------------------------------
#define ROWB   80                  // bytes per smem row (32 bf16 data + pad)
#define TILEB  (128 * ROWB)        // 10240 B
#define BUFB   (4 * TILEB)         // AHI, ALO, BHI, BLO
#define GSMEM  (2 * BUFB)          // 81920 B

template <int MODE>
__device__ __forceinline__ void hmma_gemm_body(
    const __nv_bfloat16* __restrict__ Ah, const __nv_bfloat16* __restrict__ Al,
    const __nv_bfloat16* __restrict__ Bh, const __nv_bfloat16* __restrict__ Bl,
    const float* __restrict__ bias,
    float* __restrict__ O, __nv_bfloat16* __restrict__ Ohi,
    __nv_bfloat16* __restrict__ Olo, int M)
{
    extern __shared__ char sm[];
    const uint32_t sb = smem_u32(sm);

    const int tid  = threadIdx.x;
    const int lane = tid & 31;
    const int wid  = tid >> 5;
    const int mBase = blockIdx.y * 128;
    const int nBase = blockIdx.x * 128;
    const int wm = (wid >> 2) * 64;
    const int wn = (wid & 3) * 32;

    const int a_row  = ((lane >> 3) & 1) * 8 + (lane & 7);
    const int a_koff = (lane >> 4) * 16;
    const int b_row  = ((lane >> 4) & 1) * 8 + (lane & 7);
    const int b_koff = ((lane >> 3) & 1) * 16;

    // cp.async staging: 2 threads per row, 32B each (2 x 16B)
    const int r_st  = tid >> 1;
    const int sg_st = (tid & 1) * 32;               // byte offset in 64B row chunk
    const int  arow = mBase + r_st;
    const bool aval = arow < M;
    const char* ArH = (const char*)(Ah + (size_t)(aval ? arow : 0) * CDIM);
    const char* ArL = (const char*)(Al + (size_t)(aval ? arow : 0) * CDIM);
    const char* BrH = (const char*)(Bh + (size_t)(nBase + r_st) * CDIM);
    const char* BrL = (const char*)(Bl + (size_t)(nBase + r_st) * CDIM);
    const uint32_t smoff = (uint32_t)r_st * ROWB + sg_st;
    const int asz = aval ? 16 : 0;

    float acc[4][4][4];
#pragma unroll
    for (int i = 0; i < 4; i++)
#pragma unroll
        for (int j = 0; j < 4; j++)
#pragma unroll
            for (int r = 0; r < 4; r++) acc[i][j][r] = 0.f;

    const int NC = CDIM / 32;   // 24

    // prologue: chunk 0
    {
        uint32_t d = sb + smoff;
        int gb = sg_st;
        CPA16(d, ArH + gb, asz);                 CPA16(d + 16, ArH + gb + 16, asz);
        CPA16(d + TILEB, ArL + gb, asz);         CPA16(d + TILEB + 16, ArL + gb + 16, asz);
        CPA16(d + 2 * TILEB, BrH + gb, 16);      CPA16(d + 2 * TILEB + 16, BrH + gb + 16, 16);
        CPA16(d + 3 * TILEB, BrL + gb, 16);      CPA16(d + 3 * TILEB + 16, BrL + gb + 16, 16);
        CPA_COMMIT();
    }

    for (int c = 0; c < NC; c++) {
        if (c + 1 < NC) {
            uint32_t d = sb + (uint32_t)((c + 1) & 1) * BUFB + smoff;
            int gb = (c + 1) * 64 + sg_st;
            CPA16(d, ArH + gb, asz);             CPA16(d + 16, ArH + gb + 16, asz);
            CPA16(d + TILEB, ArL + gb, asz);     CPA16(d + TILEB + 16, ArL + gb + 16, asz);
            CPA16(d + 2 * TILEB, BrH + gb, 16);  CPA16(d + 2 * TILEB + 16, BrH + gb + 16, 16);
            CPA16(d + 3 * TILEB, BrL + gb, 16);  CPA16(d + 3 * TILEB + 16, BrL + gb + 16, 16);
            CPA_COMMIT();
            CPA_WAIT(1);
        } else {
            CPA_WAIT(0);
        }
        __syncthreads();

        const uint32_t bufA = sb + (uint32_t)(c & 1) * BUFB;
        const uint32_t bufB = bufA + 2 * TILEB;
#pragma unroll
        for (int ks = 0; ks < 2; ks++) {
            uint32_t ah[4][4], al[4][4];
#pragma unroll
            for (int mt = 0; mt < 4; mt++) {
                uint32_t addr = bufA + (uint32_t)(wm + mt * 16 + a_row) * ROWB
                              + ks * 32 + a_koff;
                LDSM4(ah[mt], addr);
                LDSM4(al[mt], addr + TILEB);
            }
            uint32_t bh[4][2], bl[4][2];
#pragma unroll
            for (int np = 0; np < 2; np++) {
                uint32_t addr = bufB + (uint32_t)(wn + np * 16 + b_row) * ROWB
                              + ks * 32 + b_koff;
                uint32_t t[4];
                LDSM4(t, addr);
                bh[np * 2][0] = t[0]; bh[np * 2][1] = t[1];
                bh[np * 2 + 1][0] = t[2]; bh[np * 2 + 1][1] = t[3];
                LDSM4(t, addr + TILEB);
                bl[np * 2][0] = t[0]; bl[np * 2][1] = t[1];
                bl[np * 2 + 1][0] = t[2]; bl[np * 2 + 1][1] = t[3];
            }
#pragma unroll
            for (int mt = 0; mt < 4; mt++)
#pragma unroll
                for (int nt = 0; nt < 4; nt++) {
                    MMA16816(acc[mt][nt], ah[mt], bh[nt]);
                    MMA16816(acc[mt][nt], ah[mt], bl[nt]);
                    MMA16816(acc[mt][nt], al[mt], bh[nt]);
                }
        }
        __syncthreads();
    }

    // ---- epilogue ----
#pragma unroll
    for (int mt = 0; mt < 4; mt++) {
#pragma unroll
        for (int nt = 0; nt < 4; nt++) {
            int cc = nBase + wn + nt * 8 + (lane & 3) * 2;
            float bx = bias[cc], by = bias[cc + 1];
#pragma unroll
            for (int half = 0; half < 2; half++) {
                int m = mBase + wm + mt * 16 + (lane >> 2) + half * 8;
                if (m >= M) continue;
                float vx = acc[mt][nt][half * 2] + bx;
                float vy = acc[mt][nt][half * 2 + 1] + by;
                if (MODE == 0) {
                    int b = m / LSEQ, l = m % LSEQ;
                    int h = cc >> 6, d = cc & 63;
                    size_t off = (((size_t)b * NHEAD + h) * LSEQ + l) * HD + d;
                    uint32_t hh, ll;
                    split2(vx, vy, hh, ll);
                    *(uint32_t*)(Ohi + off) = hh;
                    *(uint32_t*)(Olo + off) = ll;
                } else {
                    *(float2*)(O + (size_t)m * CDIM + cc) = make_float2(vx, vy);
                }
            }
        }
    }
}

__global__ void __launch_bounds__(256) gemm_qkv(
    const float* __restrict__ bq, const float* __restrict__ bk,
    const float* __restrict__ bv, int M)
{
    int z = blockIdx.z;
    const float* bs = (z == 0) ? bq : ((z == 1) ? bk : bv);
    __nv_bfloat16* Oh = (z == 0) ? g_qh : ((z == 1) ? g_kh : g_vh);
    __nv_bfloat16* Ol = (z == 0) ? g_ql : ((z == 1) ? g_kl : g_vl);
    hmma_gemm_body<0>(g_xh, g_xl,
                      g_wh + (size_t)z * CDIM * CDIM, g_wl + (size_t)z * CDIM * CDIM,
                      bs, nullptr, Oh, Ol, M);
}

__global__ void __launch_bounds__(256) gemm_proj(
    const float* __restrict__ bp, float* __restrict__ out, int M)
{
    hmma_gemm_body<1>(g_yh, g_yl,
                      g_wh + (size_t)3 * CDIM * CDIM, g_wl + (size_t)3 * CDIM * CDIM,
                      bp, out, nullptr, nullptr, M);
}

// ---------------------------------------------------------------------------
// Mask: True = blocked. Mirrors build_mask for T=512, N=16.
// ---------------------------------------------------------------------------
__device__ __forceinline__ bool blocked_qk(int q, int k)
{
    if (q >= MLEN) return k < MLEN;
    if (k >= MLEN) return q < TCONST;
    int qb = q >> 9, kb = k >> 9;
    int qi = q & 511, ki = k & 511;
    if (qb == 0) return !(kb == 0 && qi >= ki);
    if (qb == 1) return (kb == 0) ? (qi < ki) : (qi <= ki);
    return (kb == 2) ? (qi <= ki) : (qi < ki);
}

// ---------------------------------------------------------------------------
// HMMA flash attention on pre-split bf16 q/k/v.
// CTA = 64 q-rows of one (b,h), 4 warps x 16 rows. P in registers.
// ---------------------------------------------------------------------------
#define FROWB 144                        // 64 dims bf16 (128B) + 16B pad
#define FTILE (64 * FROWB)               // 9216 B
#define FSMEM (4 * FTILE)                // khi, klo, vhi, vlo = 36864 B

__global__ void __launch_bounds__(128) flash_attn_mma(int B)
{
    extern __shared__ char smx[];
    const uint32_t sb  = smem_u32(smx);
    const uint32_t khi = sb;
    const uint32_t vhi = sb + 2 * FTILE;

    const int bh = blockIdx.y;
    const int b  = bh / NHEAD, h = bh % NHEAD;
    const int qt = blockIdx.x;
    const int q0 = qt * 64;

    const size_t base = ((size_t)b * NHEAD + h) * LSEQ * HD;
    const char* pKh = (const char*)(g_kh + base);
    const char* pKl = (const char*)(g_kl + base);
    const char* pVh = (const char*)(g_vh + base);
    const char* pVl = (const char*)(g_vl + base);
    const __nv_bfloat16* Qh = g_qh + base;
    const __nv_bfloat16* Ql = g_ql + base;

    const int tid  = threadIdx.x;
    const int lane = tid & 31;
    const int g    = lane >> 2;
    const int qr   = (lane & 3) * 2;

    const int b_row  = ((lane >> 4) & 1) * 8 + (lane & 7);
    const int b_koff = ((lane >> 3) & 1) * 16;

    const int qrow0 = q0 + (tid >> 5) * 16 + g;
    const int qrow1 = qrow0 + 8;

    // ---- Q fragments from pre-split arrays ----
    uint32_t qh[4][4], ql[4][4];
#pragma unroll
    for (int ks = 0; ks < 4; ks++) {
#pragma unroll
        for (int part = 0; part < 4; part++) {
            int row = (part & 1) ? qrow1 : qrow0;
            int col = ks * 16 + qr + (part >> 1) * 8;
            if (row < LSEQ) {
                qh[ks][part] = *(const uint32_t*)(Qh + (size_t)row * HD + col);
                ql[ks][part] = *(const uint32_t*)(Ql + (size_t)row * HD + col);
            } else {
                qh[ks][part] = 0; ql[ks][part] = 0;
            }
        }
    }

    float oacc[8][4];
#pragma unroll
    for (int i = 0; i < 8; i++)
#pragma unroll
        for (int r = 0; r < 4; r++) oacc[i][r] = 0.f;
    float m0 = -1e30f, m1 = -1e30f, l0 = 0.f, l1 = 0.f;

    const int nkt = 26;
    for (int kt = 0; kt < nkt; kt++) {
        bool qtext = (qt >= 24), ktext = (kt >= 24);
        bool visit;
        if (qtext)       visit = ktext;
        else if (ktext)  visit = (qt >= 8);
        else             visit = ((qt & 7) >= (kt & 7)) && !((qt < 8) && (kt >= 8));
        if (!visit) continue;

        const bool partial = (kt == 25) || (!ktext && !qtext && ((qt & 7) == (kt & 7)));
        const int k0 = kt * 64;

        // ---- load K/V tiles via cp.async (4 tiles x 4 ops/thread) ----
        __syncthreads();
        {
            const int rr  = tid >> 3;            // 0..15
            const int seg = (tid & 7) * 16;      // byte offset in 128B row
#pragma unroll
            for (int t = 0; t < 4; t++) {
                const char* src = (t == 0) ? pKh : (t == 1) ? pKl
                                : (t == 2) ? pVh : pVl;
#pragma unroll
                for (int j = 0; j < 4; j++) {
                    int r = rr + j * 16;
                    int row = k0 + r;
                    bool ok = row < LSEQ;
                    const char* gp = src + (size_t)(ok ? row : 0) * (HD * 2) + seg;
                    uint32_t d = sb + t * FTILE + (uint32_t)r * FROWB + seg;
                    CPA16(d, gp, ok ? 16 : 0);
                }
            }
        }
        CPA_COMMIT();
        CPA_WAIT(0);
        __syncthreads();

        // ---- S = Q K^T ----
        float sacc[8][4];
#pragma unroll
        for (int i = 0; i < 8; i++)
#pragma unroll
            for (int r = 0; r < 4; r++) sacc[i][r] = 0.f;
#pragma unroll
        for (int ks = 0; ks < 4; ks++) {
#pragma unroll
            for (int kg = 0; kg < 4; kg++) {
                uint32_t addr = khi + (uint32_t)(kg * 16 + b_row) * FROWB
                              + ks * 32 + b_koff;
                uint32_t th[4], tl[4];
                LDSM4(th, addr);
                LDSM4(tl, addr + FTILE);
                uint32_t bh0[2] = {th[0], th[1]}, bh1[2] = {th[2], th[3]};
                uint32_t bl0[2] = {tl[0], tl[1]}, bl1[2] = {tl[2], tl[3]};
                MMA16816(sacc[kg * 2],     qh[ks], bh0);
                MMA16816(sacc[kg * 2],     qh[ks], bl0);
                MMA16816(sacc[kg * 2],     ql[ks], bh0);
                MMA16816(sacc[kg * 2 + 1], qh[ks], bh1);
                MMA16816(sacc[kg * 2 + 1], qh[ks], bl1);
                MMA16816(sacc[kg * 2 + 1], ql[ks], bh1);
            }
        }
        // scale by 1/sqrt(64)
#pragma unroll
        for (int i = 0; i < 8; i++)
#pragma unroll
            for (int r = 0; r < 4; r++) sacc[i][r] *= 0.125f;

        // ---- mask (partial tiles only) ----
        if (partial) {
#pragma unroll
            for (int nt = 0; nt < 8; nt++) {
                int kc = k0 + nt * 8 + qr;
#pragma unroll
                for (int e = 0; e < 2; e++) {
                    int kk = kc + e;
                    bool kb = (kk >= LSEQ);
                    if (kb || qrow0 >= LSEQ || blocked_qk(qrow0, kk))
                        sacc[nt][e] = -1e30f;
                    if (kb || qrow1 >= LSEQ || blocked_qk(qrow1, kk))
                        sacc[nt][2 + e] = -1e30f;
                }
            }
        }

        // ---- online softmax ----
        float mx0 = -1e30f, mx1 = -1e30f;
#pragma unroll
        for (int nt = 0; nt < 8; nt++) {
            mx0 = fmaxf(mx0, fmaxf(sacc[nt][0], sacc[nt][1]));
            mx1 = fmaxf(mx1, fmaxf(sacc[nt][2], sacc[nt][3]));
        }
        mx0 = fmaxf(mx0, __shfl_xor_sync(0xffffffffu, mx0, 1));
        mx0 = fmaxf(mx0, __shfl_xor_sync(0xffffffffu, mx0, 2));
        mx1 = fmaxf(mx1, __shfl_xor_sync(0xffffffffu, mx1, 1));
        mx1 = fmaxf(mx1, __shfl_xor_sync(0xffffffffu, mx1, 2));

        float nm0 = fmaxf(m0, mx0), nm1 = fmaxf(m1, mx1);
        float al0 = __expf(m0 - nm0), al1 = __expf(m1 - nm1);
        m0 = nm0; m1 = nm1;

        float rs0 = 0.f, rs1 = 0.f;
        uint32_t ph[4][4], pl[4][4];
#pragma unroll
        for (int nt = 0; nt < 8; nt++) {
            float p0 = __expf(sacc[nt][0] - nm0);
            float p1 = __expf(sacc[nt][1] - nm0);
            float p2 = __expf(sacc[nt][2] - nm1);
            float p3 = __expf(sacc[nt][3] - nm1);
            rs0 += p0 + p1; rs1 += p2 + p3;
            int j = nt >> 1, half = nt & 1;
            split2(p0, p1, ph[j][half * 2],     pl[j][half * 2]);
            split2(p2, p3, ph[j][half * 2 + 1], pl[j][half * 2 + 1]);
        }
        rs0 += __shfl_xor_sync(0xffffffffu, rs0, 1);
        rs0 += __shfl_xor_sync(0xffffffffu, rs0, 2);
        rs1 += __shfl_xor_sync(0xffffffffu, rs1, 1);
        rs1 += __shfl_xor_sync(0xffffffffu, rs1, 2);
        l0 = l0 * al0 + rs0;
        l1 = l1 * al1 + rs1;

#pragma unroll
        for (int nt = 0; nt < 8; nt++) {
            oacc[nt][0] *= al0; oacc[nt][1] *= al0;
            oacc[nt][2] *= al1; oacc[nt][3] *= al1;
        }

        // ---- O += P V ----
#pragma unroll
        for (int j = 0; j < 4; j++) {
#pragma unroll
            for (int dg = 0; dg < 4; dg++) {
                uint32_t addr = vhi + (uint32_t)(j * 16 + b_row) * FROWB
                              + dg * 32 + b_koff;
                uint32_t th[4], tl[4];
                LDSM4T(th, addr);
                LDSM4T(tl, addr + FTILE);
                uint32_t bh0[2] = {th[0], th[2]}, bh1[2] = {th[1], th[3]};
                uint32_t bl0[2] = {tl[0], tl[2]}, bl1[2] = {tl[1], tl[3]};
                MMA16816(oacc[dg * 2],     ph[j], bh0);
                MMA16816(oacc[dg * 2],     ph[j], bl0);
                MMA16816(oacc[dg * 2],     pl[j], bh0);
                MMA16816(oacc[dg * 2 + 1], ph[j], bh1);
                MMA16816(oacc[dg * 2 + 1], ph[j], bl1);
                MMA16816(oacc[dg * 2 + 1], pl[j], bh1);
            }
        }
    }

    // ---- epilogue: split y to bf16 hi/lo for the output projection ----
    float inv0 = 1.f / fmaxf(l0, 1e-30f);
    float inv1 = 1.f / fmaxf(l1, 1e-30f);
#pragma unroll
    for (int nt = 0; nt < 8; nt++) {
        int d = nt * 8 + qr;
        uint32_t hh, ll;
        if (qrow0 < LSEQ) {
            size_t off = ((size_t)b * LSEQ + qrow0) * CDIM + h * HD + d;
            split2(oacc[nt][0] * inv0, oacc[nt][1] * inv0, hh, ll);
            *(uint32_t*)(g_yh + off) = hh;
            *(uint32_t*)(g_yl + off) = ll;
        }
        if (qrow1 < LSEQ) {
            size_t off = ((size_t)b * LSEQ + qrow1) * CDIM + h * HD + d;
            split2(oacc[nt][2] * inv1, oacc[nt][3] * inv1, hh, ll);
            *(uint32_t*)(g_yh + off) = hh;
            *(uint32_t*)(g_yl + off) = ll;
        }
    }
}

// ---------------------------------------------------------------------------
extern "C" void kernel_launch(void* const* d_in, const int* in_sizes, int n_in,
                              void* d_out, int out_size)
{
    const float* x  = (const float*)d_in[0];
    const float* Wq = (const float*)d_in[1];
    const float* bq = (const float*)d_in[2];
    const float* Wk = (const float*)d_in[3];
    const float* bk = (const float*)d_in[4];
    const float* Wv = (const float*)d_in[5];
    const float* bv = (const float*)d_in[6];
    const float* Wp = (const float*)d_in[7];
    const float* bp = (const float*)d_in[8];

    int B = in_sizes[0] / (LSEQ * CDIM);
    if (B < 1) B = 1;
    if (B > BMAX) B = BMAX;
    const int M = B * LSEQ;

    cudaFuncSetAttribute(gemm_qkv, cudaFuncAttributeMaxDynamicSharedMemorySize, GSMEM);
    cudaFuncSetAttribute(gemm_proj, cudaFuncAttributeMaxDynamicSharedMemorySize, GSMEM);
    cudaFuncSetAttribute(flash_attn_mma, cudaFuncAttributeMaxDynamicSharedMemorySize, FSMEM);

    // 0) pre-split inputs and weights to bf16 hi/lo
    int nx = M * CDIM;
    split_x<<<(nx / 4 + 255) / 256, 256>>>(x, nx);
    dim3 gw(CDIM * CDIM / 4 / 256, 1, 4);
    split_w<<<gw, 256>>>(Wq, Wk, Wv, Wp);

    // 1) fused QKV projections
    dim3 g1(CDIM / 128, (M + 127) / 128, 3);
    gemm_qkv<<<g1, dim3(256), GSMEM>>>(bq, bk, bv, M);

    // 2) flash attention
    dim3 g2(26, B * NHEAD);
    flash_attn_mma<<<g2, dim3(128), FSMEM>>>(B);

    // 3) output projection into d_out
    dim3 g3(CDIM / 128, (M + 127) / 128);
    gemm_proj<<<g3, dim3(256), GSMEM>>>(bp, (float*)d_out, M);
}